// round 2
// baseline (speedup 1.0000x reference)
#include <cuda_runtime.h>
#include <cstdint>

#define RR 512
#define TT 4096
#define TT4 1024
#define MM 16384
#define NNODE 2048
#define NCDF 8192
#define MAXR 64
#define XOFF (RR*TT)            /* 2097152 */
#define COFF (RR*TT)
#define YOFF (XOFF + MM*TT)     /* 69206016 */

// gemm tiling
#define TM 128      /* movements per block */
#define TN 128      /* t columns per block */
#define KC 128      /* routes per K chunk */
#define NCHUNK (RR/KC)   /* 4 */

// ---------------- scratch (device globals; no allocation) ----------------
__device__ __align__(16) unsigned short g_mov_routes[MM * MAXR]; // 2 MB
__device__ int   g_mov_cnt[MM];
__device__ int   g_node_cnt[NNODE];
__device__ int   g_node_fill[NNODE];
__device__ int   g_node_start[NNODE + 1];
__device__ int   g_node_movs[MM];
__device__ float g_node_flow[NNODE * TT];                        // 32 MB
__device__ float g_co4[NCDF];
__device__ float g_flo[NCDF];
__device__ float g_base;

__device__ __forceinline__ unsigned smem_u32(const void* p) {
    return (unsigned)__cvta_generic_to_shared(p);
}
#define CP_ASYNC16(dst, src) \
    asm volatile("cp.async.cg.shared.global [%0], [%1], 16;" :: "r"(dst), "l"(src))
#define CP_COMMIT() asm volatile("cp.async.commit_group;")
#define CP_WAIT(n)  asm volatile("cp.async.wait_group %0;" :: "n"(n))
#define ADDX2(a, b) asm("add.rn.f32x2 %0, %1, %2;" : "=l"(a) : "l"(a), "l"(b))

// ---------------- 1: relu ----------------
__global__ void k_relu(const float* __restrict__ xr, float* __restrict__ out) {
    int i = blockIdx.x * blockDim.x + threadIdx.x;   // float4 index
    if (i < RR * TT / 4) {
        float4 v = ((const float4*)xr)[i];
        v.x = fmaxf(v.x, 0.f); v.y = fmaxf(v.y, 0.f);
        v.z = fmaxf(v.z, 0.f); v.w = fmaxf(v.w, 0.f);
        ((float4*)out)[i] = v;
    }
}

// ---------------- 2: zero counters ----------------
__global__ void k_zero() {
    int i = blockIdx.x * blockDim.x + threadIdx.x;
    if (i < NNODE) { g_node_cnt[i] = 0; g_node_fill[i] = 0; }
}

// ---------------- 3: compact A rows into per-movement route lists ----------------
__global__ void k_csr_mov(const float* __restrict__ A) {
    int warp = threadIdx.x >> 5;
    int lane = threadIdx.x & 31;
    int m = blockIdx.x * 8 + warp;
    if (m >= MM) return;
    const float* row = A + (size_t)m * RR;
    unsigned base = 0;
    #pragma unroll
    for (int it = 0; it < RR / 32; ++it) {
        int r = it * 32 + lane;
        float v = row[r];
        bool nz = v > 0.5f;
        unsigned mask = __ballot_sync(0xFFFFFFFFu, nz);
        if (nz) {
            unsigned rank = __popc(mask & ((1u << lane) - 1u));
            unsigned pos = base + rank;
            if (pos < MAXR) g_mov_routes[(size_t)m * MAXR + pos] = (unsigned short)r;
        }
        base += __popc(mask);
    }
    if (lane == 0) g_mov_cnt[m] = (int)(base < MAXR ? base : MAXR);
}

// ---------------- 4: per-node movement counts ----------------
__global__ void k_node_count(const int* __restrict__ mnode) {
    int m = blockIdx.x * blockDim.x + threadIdx.x;
    if (m < MM) atomicAdd(&g_node_cnt[mnode[m]], 1);
}

// ---------------- 5: exclusive scan (single block) ----------------
__global__ void k_scan() {
    __shared__ int b0[NNODE], b1[NNODE];
    int tid = threadIdx.x;                 // 1024 threads
    b0[tid]        = g_node_cnt[tid];
    b0[tid + 1024] = g_node_cnt[tid + 1024];
    __syncthreads();
    int* src = b0; int* dst = b1;
    for (int off = 1; off < NNODE; off <<= 1) {
        #pragma unroll
        for (int k = 0; k < 2; ++k) {
            int i = tid + k * 1024;
            int v = src[i];
            if (i >= off) v += src[i - off];
            dst[i] = v;
        }
        __syncthreads();
        int* t = src; src = dst; dst = t;
    }
    g_node_start[tid + 1]    = src[tid];
    g_node_start[tid + 1025] = src[tid + 1024];
    if (tid == 0) g_node_start[0] = 0;
}

// ---------------- 6: scatter movements into node CSR ----------------
__global__ void k_scatter(const int* __restrict__ mnode) {
    int m = blockIdx.x * blockDim.x + threadIdx.x;
    if (m < MM) {
        int n = mnode[m];
        int pos = atomicAdd(&g_node_fill[n], 1);
        g_node_movs[g_node_start[n] + pos] = m;
    }
}

// ---------------- 7: main sparse GEMM: c_pred = A @ x ----------------
// block 512 thr = 16 warps. warp w handles movements m0 + w*8 + j (j=0..7),
// all 32 lanes share the route list (no divergence), each lane owns 4 t-cols.
// K is processed in 4 chunks of 128 routes, double-buffered via cp.async.
// smem: 2 x (128 rows x 128 cols x 4B = 64KB) + route lists 128x64x2B = 16KB.
__global__ void __launch_bounds__(512, 1) k_gemm(const float* __restrict__ xd,
                                                 float* __restrict__ outp) {
    extern __shared__ float smem[];
    float* xs[2] = { smem, smem + KC * TN };
    unsigned short* rts = (unsigned short*)(smem + 2 * KC * TN); // [TM][MAXR]
    int tid = threadIdx.x;
    int lane = tid & 31;
    int w = tid >> 5;
    int t0 = blockIdx.x * TN;
    int m0 = blockIdx.y * TM;

    // ---- async load: route lists + chunk0, then chunk1 ----
    {
        // route lists: TM*MAXR*2 bytes = 16KB -> 1024 x 16B
        const char* src = (const char*)(g_mov_routes + (size_t)m0 * MAXR);
        unsigned dst = smem_u32(rts);
        #pragma unroll
        for (int i = tid; i < TM * MAXR * 2 / 16; i += 512)
            CP_ASYNC16(dst + i * 16, src + i * 16);
        // chunk 0: rows [0,KC), cols [t0, t0+TN)
        #pragma unroll
        for (int i = tid; i < KC * TN / 4; i += 512) {
            int r = i >> 5, c16 = i & 31;
            CP_ASYNC16(smem_u32(xs[0] + r * TN + c16 * 4),
                       xd + (size_t)r * TT + t0 + c16 * 4);
        }
        CP_COMMIT();
        #pragma unroll
        for (int i = tid; i < KC * TN / 4; i += 512) {
            int r = i >> 5, c16 = i & 31;
            CP_ASYNC16(smem_u32(xs[1] + r * TN + c16 * 4),
                       xd + (size_t)(KC + r) * TT + t0 + c16 * 4);
        }
        CP_COMMIT();
    }

    // per-movement state
    int cnt[8], p[8];
    ulonglong2 acc[8];
    #pragma unroll
    for (int j = 0; j < 8; ++j) {
        cnt[j] = g_mov_cnt[m0 + w * 8 + j];
        p[j] = 0;
        acc[j].x = 0ULL; acc[j].y = 0ULL;
    }

    #pragma unroll
    for (int c = 0; c < NCHUNK; ++c) {
        CP_WAIT(1);
        __syncthreads();
        const float* xb = xs[c & 1];
        int kend = (c + 1) * KC;
        #pragma unroll
        for (int j = 0; j < 8; ++j) {
            const unsigned short* row = rts + (w * 8 + j) * MAXR;
            int pp = p[j], cc = cnt[j];
            ulonglong2 a = acc[j];
            while (pp < cc) {
                int r = row[pp];
                if (r >= kend) break;
                const ulonglong2 v =
                    *(const ulonglong2*)(xb + ((r - c * KC) * TN + lane * 4));
                ADDX2(a.x, v.x);
                ADDX2(a.y, v.y);
                ++pp;
            }
            acc[j] = a; p[j] = pp;
        }
        __syncthreads();
        // prefetch chunk c+2 into the buffer we just finished reading
        if (c + 2 < NCHUNK) {
            float* nb = xs[c & 1];
            #pragma unroll
            for (int i = tid; i < KC * TN / 4; i += 512) {
                int r = i >> 5, c16 = i & 31;
                CP_ASYNC16(smem_u32(nb + r * TN + c16 * 4),
                           xd + (size_t)((c + 2) * KC + r) * TT + t0 + c16 * 4);
            }
        }
        CP_COMMIT();   // keep group count consistent (empty groups are fine)
    }

    // ---- write out: each lane stores its float4 per movement ----
    ulonglong2* cp = (ulonglong2*)(outp + COFF);
    #pragma unroll
    for (int j = 0; j < 8; ++j) {
        int m = m0 + w * 8 + j;
        cp[(size_t)m * (TT / 4) + (t0 >> 2) + lane] = acc[j];
    }
}

// ---------------- 8: node_flow gather from c_pred ----------------
__global__ void k_nodeflow(const float* __restrict__ outp) {
    int n = blockIdx.x;
    int tj = blockIdx.y * blockDim.x + threadIdx.x;   // float4 col 0..1023
    const float4* cp4 = (const float4*)(outp + COFF);
    int s = g_node_start[n], e = g_node_start[n + 1];
    float4 acc = make_float4(0.f, 0.f, 0.f, 0.f);
    for (int i = s; i < e; ++i) {
        int m = g_node_movs[i];
        float4 v = cp4[(size_t)m * TT4 + tj];
        acc.x += v.x; acc.y += v.y; acc.z += v.z; acc.w += v.w;
    }
    ((float4*)g_node_flow)[(size_t)n * TT4 + tj] = acc;
}

// ---------------- 9: BPR per-row constants + base reduction ----------------
__global__ void k_prep(const float* __restrict__ tf, const float* __restrict__ cap,
                       const float* __restrict__ radio) {
    __shared__ float red[1024];
    int tid = threadIdx.x;
    float local = 0.f;
    for (int c = tid; c < NCDF; c += 1024) {
        float tfr = tf[c] * radio[c];
        float ic = 1.f / cap[c];
        float ic2 = ic * ic;
        g_co4[c] = 0.15f * tfr * ic2 * ic2;
        g_flo[c] = 1e-6f * cap[c];
        local += tfr;
    }
    red[tid] = local;
    __syncthreads();
    for (int s = 512; s > 0; s >>= 1) {
        if (tid < s) red[tid] += red[tid + s];
        __syncthreads();
    }
    if (tid == 0) g_base = red[0];
}

// ---------------- 10: init y to base ----------------
__global__ void k_ybase(float* __restrict__ outp) {
    int t = blockIdx.x * blockDim.x + threadIdx.x;
    if (t < TT) outp[YOFF + t] = g_base;
}

// ---------------- 11: y partial sums ----------------
__global__ void k_y(const int* __restrict__ cdfn, float* __restrict__ outp) {
    int t = blockIdx.x * blockDim.x + threadIdx.x;   // 8 blocks x 512 = 4096
    int c0 = blockIdx.y * 1024;
    float s = 0.f;
    #pragma unroll 4
    for (int c = c0; c < c0 + 1024; ++c) {
        int nc = __ldg(&cdfn[c]);
        float f = g_node_flow[(size_t)nc * TT + t];
        float g = fmaxf(f, g_flo[c]);
        float g2 = g * g;
        s += g_co4[c] * g2 * g2;
    }
    atomicAdd(&outp[YOFF + t], s);
}

// ---------------- launch ----------------
extern "C" void kernel_launch(void* const* d_in, const int* in_sizes, int n_in,
                              void* d_out, int out_size) {
    const float* x_raw  = (const float*)d_in[0];
    const float* A      = (const float*)d_in[1];
    const float* t_free = (const float*)d_in[2];
    const float* cap    = (const float*)d_in[3];
    const float* radio  = (const float*)d_in[4];
    const int*   mnode  = (const int*)d_in[5];
    const int*   cdfn   = (const int*)d_in[6];
    float* out = (float*)d_out;

    static bool attr_set = false;
    if (!attr_set) {
        cudaFuncSetAttribute(k_gemm, cudaFuncAttributeMaxDynamicSharedMemorySize,
                             (2 * KC * TN * 4) + TM * MAXR * 2);
        attr_set = true;
    }

    // order chosen so k_gemm is launch index 5 (ncu -s 5 -c 1 captures it)
    k_relu<<<(RR * TT / 4 + 255) / 256, 256>>>(x_raw, out);        // 0
    k_zero<<<(NNODE + 255) / 256, 256>>>();                        // 1
    k_csr_mov<<<MM / 8, 256>>>(A);                                 // 2
    k_node_count<<<MM / 256, 256>>>(mnode);                        // 3
    k_scan<<<1, 1024>>>();                                         // 4

    dim3 gg(TT / TN, MM / TM);                                     // 32 x 128
    k_gemm<<<gg, 512, (2 * KC * TN * 4) + TM * MAXR * 2>>>(out, out); // 5

    k_scatter<<<MM / 256, 256>>>(mnode);                           // 6

    dim3 gn(NNODE, 4);
    k_nodeflow<<<gn, 256>>>(out);                                  // 7

    k_prep<<<1, 1024>>>(t_free, cap, radio);                       // 8
    k_ybase<<<TT / 256, 256>>>(out);                               // 9
    dim3 gy(TT / 512, NCDF / 1024);                                // 8 x 8
    k_y<<<gy, 512>>>(cdfn, out);                                   // 10
}